// round 8
// baseline (speedup 1.0000x reference)
#include <cuda_runtime.h>
#include <cuda_fp16.h>
#include <cstdint>

#define BATCH 512
#define NTOK  256
#define MTOT  (BATCH*NTOK)
#define NTILE (MTOT/128)

// smem layout (halves)
#define LD1 136
#define LD2 264
#define OFF_PG 0
#define OFF_PV 17408
#define OFF_C  34816
#define OFF_G  68608
#define OFF_W  102400
#define SM_H   111104
#define SMEMB  (SM_H*2)     // 222208 bytes
// L0 streaming stages alias the (then-unused) C+G region
#define OFF_A4 OFF_C            // 4 stages x 128x56
#define OFF_W4 (OFF_C+28672)    // 4 stages x 32x136

__device__ __half g_w[294912];
__device__ __half g_X[(size_t)MTOT*512];
__device__ __half g_P[(size_t)MTOT*256];
__device__ int    g_slot[MTOT];
__device__ int    g_cnt;

__constant__ int WOFF[9] = {0,65536,98304,131072,163840,196608,229376,262144,294912};

__global__ void convert_w(const float* w0,const float* w1,const float* w2,const float* w3,
                          const float* w4,const float* w5,const float* w6,const float* w7)
{
    int i = blockIdx.x*blockDim.x + threadIdx.x;
    if (i == 0) g_cnt = 0;
    if (i >= 294912) return;
    const float* p[8] = {w0,w1,w2,w3,w4,w5,w6,w7};
    int s = 0;
    while (i >= WOFF[s+1]) s++;
    g_w[i] = __float2half_rn(p[s][i - WOFF[s]]);
}

__global__ void __launch_bounds__(1024) stage1(const float* __restrict__ h0,
                                               const float* __restrict__ hT)
{
    __shared__ int flg[32], pre[32];
    int warp = threadIdx.x >> 5, lane = threadIdx.x & 31;
    int tok = blockIdx.x*32 + warp;
    const float4* p0 = (const float4*)(h0 + (size_t)tok*256);
    const float4* p1 = (const float4*)(hT + (size_t)tok*256);
    float4 a0 = p0[lane], a1 = p0[lane+32];
    float4 b0 = p1[lane], b1 = p1[lane+32];
    float s = a0.x+a0.y+a0.z+a0.w + a1.x+a1.y+a1.z+a1.w;
    #pragma unroll
    for (int o = 16; o > 0; o >>= 1) s += __shfl_xor_sync(0xffffffffu, s, o);
    int act = (s > 0.0f) ? 1 : 0;
    if (lane == 0) flg[warp] = act;
    __syncthreads();
    if (threadIdx.x == 0) {
        int tot = 0;
        for (int i = 0; i < 32; i++) { pre[i] = tot; tot += flg[i]; }
        flg[0] = atomicAdd(&g_cnt, tot);
    }
    __syncthreads();
    int slot = act ? (flg[0] + pre[warp]) : -1;
    if (lane == 0) g_slot[tok] = slot;
    if (act) {
        __half2* X = (__half2*)(g_X + (size_t)slot*512);
        X[lane*2+0]   = __floats2half2_rn(a0.x, a0.y);
        X[lane*2+1]   = __floats2half2_rn(a0.z, a0.w);
        X[64+lane*2]  = __floats2half2_rn(a1.x, a1.y);
        X[65+lane*2]  = __floats2half2_rn(a1.z, a1.w);
        X[128+lane*2] = __floats2half2_rn(b0.x, b0.y);
        X[129+lane*2] = __floats2half2_rn(b0.z, b0.w);
        X[192+lane*2] = __floats2half2_rn(b1.x, b1.y);
        X[193+lane*2] = __floats2half2_rn(b1.z, b1.w);
    }
}

__device__ __forceinline__ uint32_t s2u(const void* p) {
    uint32_t a;
    asm("{ .reg .u64 t; cvta.to.shared.u64 t, %1; cvt.u32.u64 %0, t; }" : "=r"(a) : "l"(p));
    return a;
}
#define CPA(d, s) asm volatile("cp.async.cg.shared.global [%0], [%1], 16;" :: "r"(d), "l"(s))
#define CPC() asm volatile("cp.async.commit_group;" ::: "memory")
#define WG(n) asm volatile("cp.async.wait_group %0;" :: "n"(n) : "memory")

__device__ __forceinline__ void ldmA(uint32_t* a, uint32_t addr) {
    asm volatile("ldmatrix.sync.aligned.m8n8.x4.shared.b16 {%0,%1,%2,%3}, [%4];"
        : "=r"(a[0]), "=r"(a[1]), "=r"(a[2]), "=r"(a[3]) : "r"(addr));
}
__device__ __forceinline__ void ldmB(uint32_t* b, uint32_t addr) {
    asm volatile("ldmatrix.sync.aligned.m8n8.x2.trans.shared.b16 {%0,%1}, [%2];"
        : "=r"(b[0]), "=r"(b[1]) : "r"(addr));
}
__device__ __forceinline__ void mma16816(float* d, const uint32_t* a, const uint32_t* b) {
    asm volatile("mma.sync.aligned.m16n8k16.row.col.f32.f16.f16.f32 "
        "{%0,%1,%2,%3},{%4,%5,%6,%7},{%8,%9},{%0,%1,%2,%3};"
        : "+f"(d[0]), "+f"(d[1]), "+f"(d[2]), "+f"(d[3])
        : "r"(a[0]), "r"(a[1]), "r"(a[2]), "r"(a[3]), "r"(b[0]), "r"(b[1]));
}

// One layer over a 128-token tile. A from gmem (4-deep pipeline) or smem act buffer.
// actc: 0 none, 1 relu, 2 sigmoid, 3 linear+multiply-by-G -> write product to Pout.
__device__ __noinline__ void do_layer(
    __half* smh, uint32_t sb,
    const __half* Ag, int lda, int a_gmem, uint32_t aoff_h, int ldA,
    const __half* Wg, int Wn, int K, int Npass,
    const float* bias, int actc,
    uint32_t doff_h, int ldD, __half* Pout)
{
    const int tid = threadIdx.x, lane = tid & 31, warp = tid >> 5;
    const int mw = (warp >> 2) * 64, nw = (warp & 3) * 32;
    const uint32_t A4 = sb + OFF_A4*2, W4 = sb + OFF_W4*2, W2 = sb + OFF_W*2;
    const uint32_t aRow = mw + (lane & 7) + ((lane & 8) ? 8 : 0);
    const uint32_t aCol = (lane & 16) ? 8 : 0;
    const int nk = K >> 5;

    for (int p = 0; p < Npass; p++) {
        const int n0 = p * 128;
        float d[4][4][4];
        #pragma unroll
        for (int i = 0; i < 4; i++)
            #pragma unroll
            for (int j = 0; j < 4; j++)
                #pragma unroll
                for (int e = 0; e < 4; e++) d[i][j][e] = 0.0f;

        if (a_gmem) {
            #define LDG0(kc, st) do { int _k0 = (kc)*32;                               \
                _Pragma("unroll")                                                      \
                for (int t = 0; t < 2; t++) { int idx = tid + t*256;                   \
                    int r = idx >> 2, c8 = (idx & 3)*8;                                \
                    CPA(A4 + ((st)*7168 + r*56 + c8)*2, Ag + (size_t)r*lda + _k0 + c8); } \
                _Pragma("unroll")                                                      \
                for (int t = 0; t < 2; t++) { int idx = tid + t*256;                   \
                    int r = idx >> 4, c8 = (idx & 15)*8;                               \
                    CPA(W4 + ((st)*4352 + r*136 + c8)*2, Wg + (size_t)(_k0+r)*Wn + n0 + c8); } \
                CPC(); } while (0)
            LDG0(0,0); LDG0(1,1); LDG0(2,2);
            for (int k = 0; k < nk; k++) {
                if (k + 3 < nk) { LDG0(k+3, (k+3)&3); WG(3); }
                else { int left = nk - 1 - k;
                       if (left >= 3) WG(3); else if (left == 2) WG(2);
                       else if (left == 1) WG(1); else WG(0); }
                __syncthreads();
                uint32_t ab = A4 + ((k&3)*7168)*2, wb = W4 + ((k&3)*4352)*2;
                #pragma unroll
                for (int kk = 0; kk < 2; kk++) {
                    uint32_t af[4][4], bf[4][2];
                    #pragma unroll
                    for (int i = 0; i < 4; i++)
                        ldmA(af[i], ab + ((aRow + i*16)*56 + aCol + kk*16)*2);
                    #pragma unroll
                    for (int j = 0; j < 4; j++)
                        ldmB(bf[j], wb + (((lane & 15) + kk*16)*136 + nw + j*8)*2);
                    #pragma unroll
                    for (int i = 0; i < 4; i++)
                        #pragma unroll
                        for (int j = 0; j < 4; j++)
                            mma16816(d[i][j], af[i], bf[j]);
                }
                __syncthreads();
            }
        } else {
            #define LDW2(kc, st) do { int _k0 = (kc)*32;                               \
                _Pragma("unroll")                                                      \
                for (int t = 0; t < 2; t++) { int idx = tid + t*256;                   \
                    int r = idx >> 4, c8 = (idx & 15)*8;                               \
                    CPA(W2 + ((st)*4352 + r*136 + c8)*2, Wg + (size_t)(_k0+r)*Wn + n0 + c8); } \
                CPC(); } while (0)
            LDW2(0,0);
            for (int k = 0; k < nk; k++) {
                if (k + 1 < nk) { LDW2(k+1, (k+1)&1); WG(1); }
                else WG(0);
                __syncthreads();
                uint32_t ab = sb + aoff_h*2, wb = W2 + ((k&1)*4352)*2;
                #pragma unroll
                for (int kk = 0; kk < 2; kk++) {
                    uint32_t af[4][4], bf[4][2];
                    #pragma unroll
                    for (int i = 0; i < 4; i++)
                        ldmA(af[i], ab + ((aRow + i*16)*ldA + aCol + k*32 + kk*16)*2);
                    #pragma unroll
                    for (int j = 0; j < 4; j++)
                        ldmB(bf[j], wb + (((lane & 15) + kk*16)*136 + nw + j*8)*2);
                    #pragma unroll
                    for (int i = 0; i < 4; i++)
                        #pragma unroll
                        for (int j = 0; j < 4; j++)
                            mma16816(d[i][j], af[i], bf[j]);
                }
                __syncthreads();
            }
        }

        // epilogue (registers): bias + activation; store to act buffer or product->gmem
        #pragma unroll
        for (int i = 0; i < 4; i++) {
            int r0 = mw + i*16 + (lane >> 2);
            #pragma unroll
            for (int j = 0; j < 4; j++) {
                int gc = n0 + nw + j*8 + (lane & 3)*2;
                float2 bb = *(const float2*)&bias[gc];
                float v0 = d[i][j][0] + bb.x, v1 = d[i][j][1] + bb.y;
                float v2 = d[i][j][2] + bb.x, v3 = d[i][j][3] + bb.y;
                if (actc == 1) {
                    v0 = fmaxf(v0,0.f); v1 = fmaxf(v1,0.f);
                    v2 = fmaxf(v2,0.f); v3 = fmaxf(v3,0.f);
                } else if (actc == 2) {
                    v0 = 1.f/(1.f+__expf(-v0)); v1 = 1.f/(1.f+__expf(-v1));
                    v2 = 1.f/(1.f+__expf(-v2)); v3 = 1.f/(1.f+__expf(-v3));
                }
                if (actc == 3) {
                    float2 fa = __half22float2(*(__half2*)&smh[OFF_G + r0*LD2 + gc]);
                    float2 fb = __half22float2(*(__half2*)&smh[OFF_G + (r0+8)*LD2 + gc]);
                    *(__half2*)&Pout[(size_t)r0*256 + gc]     = __floats2half2_rn(v0*fa.x, v1*fa.y);
                    *(__half2*)&Pout[(size_t)(r0+8)*256 + gc] = __floats2half2_rn(v2*fb.x, v3*fb.y);
                } else {
                    *(__half2*)&smh[doff_h + r0*ldD + gc]     = __floats2half2_rn(v0, v1);
                    *(__half2*)&smh[doff_h + (r0+8)*ldD + gc] = __floats2half2_rn(v2, v3);
                }
            }
        }
        __syncthreads();
    }
}

__global__ void __launch_bounds__(256,1) fused_mlp(
    const float* gb0, const float* gb1, const float* gb2, const float* gb3,
    const float* ob0, const float* ob1, const float* ob2, const float* ob3)
{
    extern __shared__ __half smh[];
    int m0 = blockIdx.x * 128;
    if (m0 >= g_cnt) return;
    uint32_t sb = s2u(smh);
    const __half* X = g_X + (size_t)m0*512;

    // gate & value L0 (A streamed from gmem), then chains from smem
    do_layer(smh, sb, X,     512, 1, 0, 0,        g_w,        128, 512, 1, gb0, 1, OFF_PG, LD1, nullptr);
    do_layer(smh, sb, X+256, 512, 1, 0, 0,        g_w+163840, 128, 256, 1, ob0, 1, OFF_PV, LD1, nullptr);
    do_layer(smh, sb, 0, 0, 0, OFF_PG, LD1,       g_w+65536,  256, 128, 2, gb1, 1, OFF_C,  LD2, nullptr);
    do_layer(smh, sb, 0, 0, 0, OFF_C,  LD2,       g_w+98304,  128, 256, 1, gb2, 1, OFF_PG, LD1, nullptr);
    do_layer(smh, sb, 0, 0, 0, OFF_PG, LD1,       g_w+131072, 256, 128, 2, gb3, 2, OFF_G,  LD2, nullptr);
    do_layer(smh, sb, 0, 0, 0, OFF_PV, LD1,       g_w+196608, 256, 128, 2, ob1, 1, OFF_C,  LD2, nullptr);
    do_layer(smh, sb, 0, 0, 0, OFF_C,  LD2,       g_w+229376, 128, 256, 1, ob2, 1, OFF_PV, LD1, nullptr);
    do_layer(smh, sb, 0, 0, 0, OFF_PV, LD1,       g_w+262144, 256, 128, 2, ob3, 3, 0, 0, g_P + (size_t)m0*256);
}

__global__ void reduce_k(float* __restrict__ out)
{
    int b = blockIdx.x, c = threadIdx.x;
    float acc = 0.0f;
    #pragma unroll 4
    for (int n = 0; n < NTOK; n++) {
        int s = g_slot[b*NTOK + n];
        if (s >= 0) acc += __half2float(g_P[(size_t)s*256 + c]);
    }
    out[b*256 + c] = acc;
}

extern "C" void kernel_launch(void* const* d_in, const int* in_sizes, int n_in,
                              void* d_out, int out_size)
{
    const float* h0 = (const float*)d_in[0];
    const float* hT = (const float*)d_in[1];
    const float* W[8]  = { (const float*)d_in[2],  (const float*)d_in[4],
                           (const float*)d_in[6],  (const float*)d_in[8],
                           (const float*)d_in[10], (const float*)d_in[12],
                           (const float*)d_in[14], (const float*)d_in[16] };
    const float* bs[8] = { (const float*)d_in[3],  (const float*)d_in[5],
                           (const float*)d_in[7],  (const float*)d_in[9],
                           (const float*)d_in[11], (const float*)d_in[13],
                           (const float*)d_in[15], (const float*)d_in[17] };
    float* out = (float*)d_out;

    convert_w<<<(294912+255)/256, 256>>>(W[0],W[1],W[2],W[3],W[4],W[5],W[6],W[7]);
    stage1<<<MTOT/32, 1024>>>(h0, hT);

    cudaFuncSetAttribute(fused_mlp, cudaFuncAttributeMaxDynamicSharedMemorySize, SMEMB);
    fused_mlp<<<NTILE, 256, SMEMB>>>(bs[0], bs[1], bs[2], bs[3],
                                     bs[4], bs[5], bs[6], bs[7]);
    reduce_k<<<BATCH, 256>>>(out);
}

// round 9
// speedup vs baseline: 1.3948x; 1.3948x over previous
#include <cuda_runtime.h>
#include <cuda_fp16.h>
#include <cstdint>

#define BATCH 512
#define NTOK  256
#define MTOT  (BATCH*NTOK)
#define NTILE (MTOT/128)

__device__ __half g_w[294912];
__device__ __half g_X [(size_t)MTOT*512];
__device__ __half g_Bg[(size_t)MTOT*128];
__device__ __half g_Cg[(size_t)MTOT*256];
__device__ __half g_G [(size_t)MTOT*256];
__device__ __half g_Bv[(size_t)MTOT*128];
__device__ __half g_Cv[(size_t)MTOT*256];
__device__ int    g_slot[MTOT];
__device__ int    g_cnt;
__device__ __half* g_bufs[6];

__constant__ int WOFF[9] = {0,65536,98304,131072,163840,196608,229376,262144,294912};

__global__ void convert_w(const float* w0,const float* w1,const float* w2,const float* w3,
                          const float* w4,const float* w5,const float* w6,const float* w7)
{
    int i = blockIdx.x*blockDim.x + threadIdx.x;
    if (i == 0) {
        g_cnt = 0;
        g_bufs[0]=g_X; g_bufs[1]=g_Bg; g_bufs[2]=g_Cg;
        g_bufs[3]=g_G; g_bufs[4]=g_Bv; g_bufs[5]=g_Cv;
    }
    if (i >= 294912) return;
    const float* p[8] = {w0,w1,w2,w3,w4,w5,w6,w7};
    int s = 0;
    while (i >= WOFF[s+1]) s++;
    g_w[i] = __float2half_rn(p[s][i - WOFF[s]]);
}

__global__ void __launch_bounds__(1024) stage1(const float* __restrict__ h0,
                                               const float* __restrict__ hT)
{
    __shared__ int flg[32], pre[32];
    int warp = threadIdx.x >> 5, lane = threadIdx.x & 31;
    int tok = blockIdx.x*32 + warp;
    const float4* p0 = (const float4*)(h0 + (size_t)tok*256);
    const float4* p1 = (const float4*)(hT + (size_t)tok*256);
    float4 a0 = p0[lane], a1 = p0[lane+32];
    float4 b0 = p1[lane], b1 = p1[lane+32];
    float s = a0.x+a0.y+a0.z+a0.w + a1.x+a1.y+a1.z+a1.w;
    #pragma unroll
    for (int o = 16; o > 0; o >>= 1) s += __shfl_xor_sync(0xffffffffu, s, o);
    int act = (s > 0.0f) ? 1 : 0;
    if (lane == 0) flg[warp] = act;
    __syncthreads();
    if (threadIdx.x == 0) {
        int tot = 0;
        for (int i = 0; i < 32; i++) { pre[i] = tot; tot += flg[i]; }
        flg[0] = atomicAdd(&g_cnt, tot);
    }
    __syncthreads();
    int slot = act ? (flg[0] + pre[warp]) : -1;
    if (lane == 0) g_slot[tok] = slot;
    if (act) {
        __half2* X = (__half2*)(g_X + (size_t)slot*512);
        X[lane*2+0]   = __floats2half2_rn(a0.x, a0.y);
        X[lane*2+1]   = __floats2half2_rn(a0.z, a0.w);
        X[64+lane*2]  = __floats2half2_rn(a1.x, a1.y);
        X[65+lane*2]  = __floats2half2_rn(a1.z, a1.w);
        X[128+lane*2] = __floats2half2_rn(b0.x, b0.y);
        X[129+lane*2] = __floats2half2_rn(b0.z, b0.w);
        X[192+lane*2] = __floats2half2_rn(b1.x, b1.y);
        X[193+lane*2] = __floats2half2_rn(b1.z, b1.w);
    }
}

__device__ __forceinline__ uint32_t s2u(const void* p) {
    uint32_t a;
    asm("{ .reg .u64 t; cvta.to.shared.u64 t, %1; cvt.u32.u64 %0, t; }" : "=r"(a) : "l"(p));
    return a;
}
#define CPA(d, s) asm volatile("cp.async.cg.shared.global [%0], [%1], 16;" :: "r"(d), "l"(s))
#define CPC() asm volatile("cp.async.commit_group;" ::: "memory")

#define LDA_S 88
#define LDB_S 136
#define SA_ST (128*LDA_S)
#define SB_ST (64*LDB_S)
#define SMEMB ((2*SA_ST + 2*SB_ST)*2)

__device__ __forceinline__ void ldmA(uint32_t* a, uint32_t addr) {
    asm volatile("ldmatrix.sync.aligned.m8n8.x4.shared.b16 {%0,%1,%2,%3}, [%4];"
        : "=r"(a[0]), "=r"(a[1]), "=r"(a[2]), "=r"(a[3]) : "r"(addr));
}
__device__ __forceinline__ void ldmB(uint32_t* b, uint32_t addr) {
    asm volatile("ldmatrix.sync.aligned.m8n8.x2.trans.shared.b16 {%0,%1}, [%2];"
        : "=r"(b[0]), "=r"(b[1]) : "r"(addr));
}
__device__ __forceinline__ void mma16816(float* d, const uint32_t* a, const uint32_t* b) {
    asm volatile("mma.sync.aligned.m16n8k16.row.col.f32.f16.f16.f32 "
        "{%0,%1,%2,%3},{%4,%5,%6,%7},{%8,%9},{%0,%1,%2,%3};"
        : "+f"(d[0]), "+f"(d[1]), "+f"(d[2]), "+f"(d[3])
        : "r"(a[0]), "r"(a[1]), "r"(a[2]), "r"(a[3]), "r"(b[0]), "r"(b[1]));
}

__global__ void __launch_bounds__(256,2) gemm_k(
    int asel0, int aoff0, int lda0, int woff0, int K0, const float* b0p, int csel0, int act0,
    int asel1, int aoff1, int lda1, int woff1, int K1, const float* b1p, int csel1, int act1,
    int N)
{
    extern __shared__ __half sm[];
    __half* sA = sm;
    __half* sB = sm + 2*SA_ST;
    int m0 = blockIdx.x * 128;
    if (m0 >= g_cnt) return;

    int asel, aoff, lda, woff, K, csel, act; const float* bias;
    if (blockIdx.z == 0) { asel=asel0; aoff=aoff0; lda=lda0; woff=woff0; K=K0; bias=b0p; csel=csel0; act=act0; }
    else                 { asel=asel1; aoff=aoff1; lda=lda1; woff=woff1; K=K1; bias=b1p; csel=csel1; act=act1; }

    const __half* __restrict__ A = g_bufs[asel] + (size_t)m0*lda + aoff;
    const __half* __restrict__ W = g_w + woff;
    __half* __restrict__ Co = g_bufs[csel];
    const int n0 = blockIdx.y * 128;
    const int tid = threadIdx.x, warp = tid >> 5, lane = tid & 31;
    const int mw = (warp >> 2) * 64;
    const int nw = (warp & 3) * 32;
    const uint32_t sAu = s2u(sA), sBu = s2u(sB);

    float d[4][4][4];
    #pragma unroll
    for (int i = 0; i < 4; i++)
        #pragma unroll
        for (int j = 0; j < 4; j++)
            #pragma unroll
            for (int e = 0; e < 4; e++) d[i][j][e] = 0.0f;

    const int nk = K >> 6;

    #define LOAD_STAGE(st, kc) do {                                                  \
        int _k0 = (kc) * 64;                                                         \
        _Pragma("unroll")                                                            \
        for (int t = 0; t < 4; t++) {                                                \
            int idx = tid + t*256;                                                   \
            int r = idx >> 3, c8 = (idx & 7) * 8;                                    \
            CPA(sAu + ((st)*SA_ST + r*LDA_S + c8)*2, A + (size_t)r*lda + _k0 + c8);  \
        }                                                                            \
        _Pragma("unroll")                                                            \
        for (int t = 0; t < 4; t++) {                                                \
            int idx = tid + t*256;                                                   \
            int r = idx >> 4, c8 = (idx & 15) * 8;                                   \
            CPA(sBu + ((st)*SB_ST + r*LDB_S + c8)*2, W + (size_t)(_k0+r)*N + n0 + c8); \
        }                                                                            \
        CPC();                                                                       \
    } while (0)

    const uint32_t aRow = mw + (lane & 7) + ((lane & 8) ? 8 : 0);
    const uint32_t aCol = (lane & 16) ? 8 : 0;
    const uint32_t aBase = sAu + (aRow * LDA_S + aCol) * 2;
    const uint32_t bBase = sBu + ((lane & 15) * LDB_S + nw) * 2;

    LOAD_STAGE(0, 0);
    for (int k = 0; k < nk; k++) {
        if (k + 1 < nk) {
            LOAD_STAGE((k+1) & 1, k+1);
            asm volatile("cp.async.wait_group 1;" ::: "memory");
        } else {
            asm volatile("cp.async.wait_group 0;" ::: "memory");
        }
        __syncthreads();
        const uint32_t aS = aBase + ((k & 1) * SA_ST) * 2;
        const uint32_t bS = bBase + ((k & 1) * SB_ST) * 2;
        #pragma unroll
        for (int kk = 0; kk < 4; kk++) {
            uint32_t af[4][4], bf[4][2];
            #pragma unroll
            for (int i = 0; i < 4; i++)
                ldmA(af[i], aS + (i*16*LDA_S + kk*16) * 2);
            #pragma unroll
            for (int j = 0; j < 4; j++)
                ldmB(bf[j], bS + (kk*16*LDB_S + j*8) * 2);
            #pragma unroll
            for (int i = 0; i < 4; i++)
                #pragma unroll
                for (int j = 0; j < 4; j++)
                    mma16816(d[i][j], af[i], bf[j]);
        }
        __syncthreads();
    }

    #pragma unroll
    for (int i = 0; i < 4; i++) {
        int row = m0 + mw + i*16 + (lane >> 2);
        #pragma unroll
        for (int j = 0; j < 4; j++) {
            int gcol = n0 + nw + j*8 + (lane & 3)*2;
            float2 bb = *(const float2*)&bias[gcol];
            float v0 = d[i][j][0] + bb.x, v1 = d[i][j][1] + bb.y;
            float v2 = d[i][j][2] + bb.x, v3 = d[i][j][3] + bb.y;
            if (act == 1) {
                v0 = fmaxf(v0,0.f); v1 = fmaxf(v1,0.f);
                v2 = fmaxf(v2,0.f); v3 = fmaxf(v3,0.f);
            } else if (act == 2) {
                v0 = 1.f/(1.f+__expf(-v0)); v1 = 1.f/(1.f+__expf(-v1));
                v2 = 1.f/(1.f+__expf(-v2)); v3 = 1.f/(1.f+__expf(-v3));
            }
            *(__half2*)&Co[(size_t)row*N + gcol]     = __floats2half2_rn(v0, v1);
            *(__half2*)&Co[(size_t)(row+8)*N + gcol] = __floats2half2_rn(v2, v3);
        }
    }
}

// parallel deterministic reduce: block (128,4); y-subgroup g handles tokens
// [g*64, g*64+64); thread x handles column pair 2x; fixed-order tree combine.
__global__ void __launch_bounds__(512) reduce_k(float* __restrict__ out)
{
    __shared__ float2 part[4][128];
    const int b = blockIdx.x, tx = threadIdx.x, ty = threadIdx.y;
    const int* __restrict__ sl = g_slot + b*NTOK + ty*64;
    float2 acc = make_float2(0.f, 0.f);
    #pragma unroll 8
    for (int t = 0; t < 64; t++) {
        int s = sl[t];
        if (s >= 0) {
            float2 fg = __half22float2(*(const __half2*)&g_G [(size_t)s*256 + 2*tx]);
            float2 fv = __half22float2(*(const __half2*)&g_Cv[(size_t)s*256 + 2*tx]);
            acc.x += fg.x * fv.x;
            acc.y += fg.y * fv.y;
        }
    }
    part[ty][tx] = acc;
    __syncthreads();
    if (ty == 0) {
        float2 r = part[0][tx];
        #pragma unroll
        for (int g = 1; g < 4; g++) { r.x += part[g][tx].x; r.y += part[g][tx].y; }
        *(float2*)&out[b*256 + 2*tx] = r;
    }
}

extern "C" void kernel_launch(void* const* d_in, const int* in_sizes, int n_in,
                              void* d_out, int out_size)
{
    const float* h0 = (const float*)d_in[0];
    const float* hT = (const float*)d_in[1];
    const float* W[8]  = { (const float*)d_in[2],  (const float*)d_in[4],
                           (const float*)d_in[6],  (const float*)d_in[8],
                           (const float*)d_in[10], (const float*)d_in[12],
                           (const float*)d_in[14], (const float*)d_in[16] };
    const float* bs[8] = { (const float*)d_in[3],  (const float*)d_in[5],
                           (const float*)d_in[7],  (const float*)d_in[9],
                           (const float*)d_in[11], (const float*)d_in[13],
                           (const float*)d_in[15], (const float*)d_in[17] };
    float* out = (float*)d_out;

    convert_w<<<(294912+255)/256, 256>>>(W[0],W[1],W[2],W[3],W[4],W[5],W[6],W[7]);
    stage1<<<MTOT/32, 1024>>>(h0, hT);

    cudaFuncSetAttribute(gemm_k, cudaFuncAttributeMaxDynamicSharedMemorySize, SMEMB);

    gemm_k<<<dim3(NTILE,1,2), 256, SMEMB>>>(
        0,   0, 512,      0, 512, bs[0], 1, 1,
        0, 256, 512, 163840, 256, bs[4], 4, 1, 128);
    gemm_k<<<dim3(NTILE,2,2), 256, SMEMB>>>(
        1, 0, 128,  65536, 128, bs[1], 2, 1,
        4, 0, 128, 196608, 128, bs[5], 5, 1, 256);
    gemm_k<<<dim3(NTILE,1,2), 256, SMEMB>>>(
        2, 0, 256,  98304, 256, bs[2], 1, 1,
        5, 0, 256, 229376, 256, bs[6], 4, 1, 128);
    gemm_k<<<dim3(NTILE,2,2), 256, SMEMB>>>(
        1, 0, 128, 131072, 128, bs[3], 3, 2,
        4, 0, 128, 262144, 128, bs[7], 5, 0, 256);

    reduce_k<<<BATCH, dim3(128,4)>>>(out);
}